// round 4
// baseline (speedup 1.0000x reference)
#include <cuda_runtime.h>
#include <cuda_bf16.h>
#include <cstdint>

#define D            128
#define S            16
#define WARPS_PB     16
#define ITEM_TILE    2
#define ITEMS_PB     (WARPS_PB * ITEM_TILE)   // 32
#define BLOCK_THREADS (WARPS_PB * 32)         // 512

// smem: W (16384 floats) + per-warp duplicated-x buffers (ITEM_TILE*D*2 floats each)
#define XDUP_FLOATS  (ITEM_TILE * D * 2)      // 512
#define SMEM_FLOATS  (D * D + WARPS_PB * XDUP_FLOATS)   // 24576
#define SMEM_BYTES   (SMEM_FLOATS * 4)        // 98304 B -> 2 blocks/SM (192KB)

__device__ __forceinline__ unsigned long long pack2(float a, float b) {
    unsigned long long r;
    asm("mov.b64 %0, {%1, %2};" : "=l"(r) : "f"(a), "f"(b));
    return r;
}
__device__ __forceinline__ void unpack2(unsigned long long v, float& a, float& b) {
    asm("mov.b64 {%0, %1}, %2;" : "=f"(a), "=f"(b) : "l"(v));
}
__device__ __forceinline__ unsigned long long fma2(unsigned long long a,
                                                   unsigned long long b,
                                                   unsigned long long c) {
    unsigned long long d;
    asm("fma.rn.f32x2 %0, %1, %2, %3;" : "=l"(d) : "l"(a), "l"(b), "l"(c));
    return d;
}

__global__ __launch_bounds__(BLOCK_THREADS, 2)   // forces regs <= 64 -> 32 warps/SM
void kgcn_kernel(const int* __restrict__ u,
                 const int* __restrict__ v,
                 const int* __restrict__ adj_ent,
                 const int* __restrict__ adj_rel,
                 const float* __restrict__ usr,
                 const float* __restrict__ ent,
                 const float* __restrict__ rel,
                 const float* __restrict__ W,
                 const float* __restrict__ bias,
                 float* __restrict__ out,
                 int B)
{
    extern __shared__ float smem[];
    float* Wsh = smem;                                   // 16384 floats

    const int tid  = threadIdx.x;
    const int lane = tid & 31;
    const int wid  = tid >> 5;

    // ---- stage W into shared (row-major W[i*128 + j]) ----
    {
        const float4* Wg4 = (const float4*)W;
        float4* Ws4 = (float4*)Wsh;
        for (int i = tid; i < (D * D) / 4; i += BLOCK_THREADS)
            Ws4[i] = Wg4[i];
    }
    __syncthreads();

    float* xd = smem + D * D + wid * XDUP_FLOATS;        // per-warp duplicated x

    const int base = (blockIdx.x * WARPS_PB + wid) * ITEM_TILE;

    const float4* usr4 = (const float4*)usr;
    const float4* ent4 = (const float4*)ent;
    const float4* rel4 = (const float4*)rel;

    // Lane owns dims j = lane*4 + m (float4 per lane) -- consistent everywhere.
    float4 mg[ITEM_TILE];    // normalized attention-weighted neighbor message

    #pragma unroll
    for (int t = 0; t < ITEM_TILE; t++) {
        const int item = base + t;
        const int cit  = item < B ? item : (B - 1);   // clamp (deterministic)
        const int iu = u[cit];
        const int iv = v[cit];

        const float4 uex = usr4[(size_t)iu * 32 + lane];
        const float4 rp  = ent4[(size_t)iv * 32 + lane];

        // Fused single-pass: score -> exp -> weighted-accumulate.
        // Scores are tiny (|p| << 1) so exp without max-subtraction is exact enough.
        float sum = 0.f;
        float4 msg = make_float4(0.f, 0.f, 0.f, 0.f);
        #pragma unroll
        for (int s = 0; s < S; s++) {
            const int ridx = __ldg(&adj_rel[iv * S + s]);
            const int eidx = __ldg(&adj_ent[iv * S + s]);
            const float4 r4 = rel4[(size_t)ridx * 32 + lane];
            const float4 e4 = ent4[(size_t)eidx * 32 + lane];  // issued early, used late
            float p = uex.x * r4.x + uex.y * r4.y + uex.z * r4.z + uex.w * r4.w;
            #pragma unroll
            for (int o = 16; o > 0; o >>= 1)
                p += __shfl_xor_sync(0xffffffffu, p, o);
            const float es = __expf(p);
            sum += es;
            msg.x = fmaf(es, e4.x, msg.x);
            msg.y = fmaf(es, e4.y, msg.y);
            msg.z = fmaf(es, e4.z, msg.z);
            msg.w = fmaf(es, e4.w, msg.w);
        }
        const float inv = __frcp_rn(sum);
        msg.x *= inv; msg.y *= inv; msg.z *= inv; msg.w *= inv;
        mg[t] = msg;

        // x0 = msg + rep0 -> shared, DUPLICATED ({x,x} pairs) for packed broadcast
        const float x0 = msg.x + rp.x, x1 = msg.y + rp.y;
        const float x2 = msg.z + rp.z, x3 = msg.w + rp.w;
        float4* dst = (float4*)(xd + t * (2 * D) + lane * 8);
        dst[0] = make_float4(x0, x0, x1, x1);
        dst[1] = make_float4(x2, x2, x3, x3);
    }
    __syncwarp();

    const float4 b4 = ((const float4*)bias)[lane];
    const unsigned long long bp0 = pack2(b4.x, b4.y);
    const unsigned long long bp1 = pack2(b4.z, b4.w);
    unsigned long long acc[ITEM_TILE][2];

    // ---- 2 iterations: rep = relu((msg + rep) @ W + b), packed f32x2 FMA ----
    #pragma unroll
    for (int iter = 0; iter < 2; iter++) {
        #pragma unroll
        for (int t = 0; t < ITEM_TILE; t++) { acc[t][0] = bp0; acc[t][1] = bp1; }

        #pragma unroll 8
        for (int i2 = 0; i2 < D / 2; i2++) {
            const float* wrow = Wsh + (2 * i2) * D + lane * 4;
            const ulonglong2 wA = *(const ulonglong2*)(wrow);       // W[2i2  ][j pairs]
            const ulonglong2 wB = *(const ulonglong2*)(wrow + D);   // W[2i2+1][j pairs]
            #pragma unroll
            for (int t = 0; t < ITEM_TILE; t++) {
                const ulonglong2 xp = *(const ulonglong2*)(xd + t * (2 * D) + i2 * 4);
                acc[t][0] = fma2(xp.x, wA.x, acc[t][0]);
                acc[t][1] = fma2(xp.x, wA.y, acc[t][1]);
                acc[t][0] = fma2(xp.y, wB.x, acc[t][0]);
                acc[t][1] = fma2(xp.y, wB.y, acc[t][1]);
            }
        }

        if (iter == 0) {
            __syncwarp();   // all lanes done reading xd before overwrite
            #pragma unroll
            for (int t = 0; t < ITEM_TILE; t++) {
                float a0, a1, a2, a3;
                unpack2(acc[t][0], a0, a1);
                unpack2(acc[t][1], a2, a3);
                const float x0 = mg[t].x + fmaxf(a0, 0.f);
                const float x1 = mg[t].y + fmaxf(a1, 0.f);
                const float x2 = mg[t].z + fmaxf(a2, 0.f);
                const float x3 = mg[t].w + fmaxf(a3, 0.f);
                float4* dst = (float4*)(xd + t * (2 * D) + lane * 8);
                dst[0] = make_float4(x0, x0, x1, x1);
                dst[1] = make_float4(x2, x2, x3, x3);
            }
            __syncwarp();
        }
    }

    // ---- final: sigmoid(dot(u_emb, relu(rep))); reload u_emb (L2-resident) ----
    #pragma unroll
    for (int t = 0; t < ITEM_TILE; t++) {
        const int item = base + t;
        const int cit  = item < B ? item : (B - 1);
        const int iu = u[cit];
        const float4 uex = usr4[(size_t)iu * 32 + lane];

        float a0, a1, a2, a3;
        unpack2(acc[t][0], a0, a1);
        unpack2(acc[t][1], a2, a3);
        float p = uex.x * fmaxf(a0, 0.f)
                + uex.y * fmaxf(a1, 0.f)
                + uex.z * fmaxf(a2, 0.f)
                + uex.w * fmaxf(a3, 0.f);
        #pragma unroll
        for (int o = 16; o > 0; o >>= 1)
            p += __shfl_xor_sync(0xffffffffu, p, o);
        if (lane == 0 && item < B)
            out[item] = 1.f / (1.f + __expf(-p));
    }
}

extern "C" void kernel_launch(void* const* d_in, const int* in_sizes, int n_in,
                              void* d_out, int out_size)
{
    const int*   u       = (const int*)d_in[0];
    const int*   v       = (const int*)d_in[1];
    const int*   adj_ent = (const int*)d_in[2];
    const int*   adj_rel = (const int*)d_in[3];
    const float* usr     = (const float*)d_in[4];
    const float* ent     = (const float*)d_in[5];
    const float* rel     = (const float*)d_in[6];
    const float* W       = (const float*)d_in[7];
    const float* bias    = (const float*)d_in[8];
    float* out = (float*)d_out;

    const int B = in_sizes[0];

    static bool attr_set = false;
    if (!attr_set) {
        cudaFuncSetAttribute(kgcn_kernel,
                             cudaFuncAttributeMaxDynamicSharedMemorySize,
                             SMEM_BYTES);
        attr_set = true;
    }

    dim3 grid((B + ITEMS_PB - 1) / ITEMS_PB);   // 256 blocks, 2/SM, warp-balanced
    kgcn_kernel<<<grid, BLOCK_THREADS, SMEM_BYTES>>>(
        u, v, adj_ent, adj_rel, usr, ent, rel, W, bias, out, B);
}

// round 5
// speedup vs baseline: 1.1344x; 1.1344x over previous
#include <cuda_runtime.h>
#include <cuda_bf16.h>
#include <cstdint>

#define D            128
#define S            16
#define WARPS_PB     8
#define ITEM_TILE    4
#define ITEMS_PB     (WARPS_PB * ITEM_TILE)   // 32
#define BLOCK_THREADS (WARPS_PB * 32)         // 256

// smem: W (16384 floats) + per-warp duplicated-x buffers
#define XDUP_FLOATS  (ITEM_TILE * D * 2)      // 1024
#define SMEM_FLOATS  (D * D + WARPS_PB * XDUP_FLOATS)   // 24576
#define SMEM_BYTES   (SMEM_FLOATS * 4)        // 98304 -> 2 blocks/SM (192KB)

__device__ __forceinline__ unsigned long long pack2(float a, float b) {
    unsigned long long r;
    asm("mov.b64 %0, {%1, %2};" : "=l"(r) : "f"(a), "f"(b));
    return r;
}
__device__ __forceinline__ void unpack2(unsigned long long v, float& a, float& b) {
    asm("mov.b64 {%0, %1}, %2;" : "=f"(a), "=f"(b) : "l"(v));
}
__device__ __forceinline__ unsigned long long fma2(unsigned long long a,
                                                   unsigned long long b,
                                                   unsigned long long c) {
    unsigned long long d;
    asm("fma.rn.f32x2 %0, %1, %2, %3;" : "=l"(d) : "l"(a), "l"(b), "l"(c));
    return d;
}

__global__ __launch_bounds__(BLOCK_THREADS, 2)    // 2 blocks/SM -> 16 warps/SM
void kgcn_kernel(const int* __restrict__ u,
                 const int* __restrict__ v,
                 const int* __restrict__ adj_ent,
                 const int* __restrict__ adj_rel,
                 const float* __restrict__ usr,
                 const float* __restrict__ ent,
                 const float* __restrict__ rel,
                 const float* __restrict__ W,
                 const float* __restrict__ bias,
                 float* __restrict__ out,
                 int B)
{
    extern __shared__ float smem[];
    float* Wsh = smem;                                   // 16384 floats

    const int tid  = threadIdx.x;
    const int lane = tid & 31;
    const int wid  = tid >> 5;

    // ---- stage W into shared (row-major W[i*128 + j]) ----
    {
        const float4* Wg4 = (const float4*)W;
        float4* Ws4 = (float4*)Wsh;
        #pragma unroll
        for (int k = 0; k < (D * D / 4) / BLOCK_THREADS; k++) {
            int i = tid + k * BLOCK_THREADS;
            Ws4[i] = Wg4[i];
        }
    }
    __syncthreads();

    float* xd = smem + D * D + wid * XDUP_FLOATS;        // per-warp duplicated x

    const int base = (blockIdx.x * WARPS_PB + wid) * ITEM_TILE;

    const float4* usr4 = (const float4*)usr;
    const float4* ent4 = (const float4*)ent;
    const float4* rel4 = (const float4*)rel;
    const int4*   adjE4 = (const int4*)adj_ent;          // 4 int4 per row of S=16
    const int4*   adjR4 = (const int4*)adj_rel;

    float4 mg[ITEM_TILE];    // normalized attention-weighted neighbor message

    #pragma unroll
    for (int t = 0; t < ITEM_TILE; t++) {
        const int item = base + t;
        const int cit  = item < B ? item : (B - 1);   // clamp (deterministic)
        const int iu = u[cit];
        const int iv = v[cit];

        const float4 uex = usr4[(size_t)iu * 32 + lane];
        const float4 rp  = ent4[(size_t)iv * 32 + lane];

        // adjacency rows as int4 broadcasts (8 LDG.128 instead of 32 LDG.32)
        int eix[S], rix[S];
        #pragma unroll
        for (int q = 0; q < 4; q++) {
            const int4 e = __ldg(&adjE4[iv * 4 + q]);
            const int4 r = __ldg(&adjR4[iv * 4 + q]);
            eix[q*4+0] = e.x; eix[q*4+1] = e.y; eix[q*4+2] = e.z; eix[q*4+3] = e.w;
            rix[q*4+0] = r.x; rix[q*4+1] = r.y; rix[q*4+2] = r.z; rix[q*4+3] = r.w;
        }

        // Fused single-pass: score -> exp -> weighted accumulate.
        // Scores are tiny (|p| << 1): exp without max-subtraction is safe.
        float sum = 0.f;
        float4 msg = make_float4(0.f, 0.f, 0.f, 0.f);
        #pragma unroll
        for (int s = 0; s < S; s++) {
            const float4 r4 = rel4[(size_t)rix[s] * 32 + lane];
            const float4 e4 = ent4[(size_t)eix[s] * 32 + lane];  // in flight with r4
            float p = uex.x * r4.x + uex.y * r4.y + uex.z * r4.z + uex.w * r4.w;
            #pragma unroll
            for (int o = 16; o > 0; o >>= 1)
                p += __shfl_xor_sync(0xffffffffu, p, o);
            const float es = __expf(p);
            sum += es;
            msg.x = fmaf(es, e4.x, msg.x);
            msg.y = fmaf(es, e4.y, msg.y);
            msg.z = fmaf(es, e4.z, msg.z);
            msg.w = fmaf(es, e4.w, msg.w);
        }
        const float inv = __frcp_rn(sum);
        msg.x *= inv; msg.y *= inv; msg.z *= inv; msg.w *= inv;
        mg[t] = msg;

        // x0 = msg + rep0 -> shared, DUPLICATED ({x,x} pairs) for packed broadcast
        const float x0 = msg.x + rp.x, x1 = msg.y + rp.y;
        const float x2 = msg.z + rp.z, x3 = msg.w + rp.w;
        float4* dst = (float4*)(xd + t * (2 * D) + lane * 8);
        dst[0] = make_float4(x0, x0, x1, x1);
        dst[1] = make_float4(x2, x2, x3, x3);
    }
    __syncwarp();

    const float4 b4 = ((const float4*)bias)[lane];
    const unsigned long long bp0 = pack2(b4.x, b4.y);
    const unsigned long long bp1 = pack2(b4.z, b4.w);
    unsigned long long acc[ITEM_TILE][2];

    // ---- 2 iterations: rep = relu((msg + rep) @ W + b), packed f32x2 FMA ----
    #pragma unroll
    for (int iter = 0; iter < 2; iter++) {
        #pragma unroll
        for (int t = 0; t < ITEM_TILE; t++) { acc[t][0] = bp0; acc[t][1] = bp1; }

        #pragma unroll 4
        for (int i2 = 0; i2 < D / 2; i2++) {
            const float* wrow = Wsh + (2 * i2) * D + lane * 4;
            const ulonglong2 wA = *(const ulonglong2*)(wrow);       // W[2i2  ][j pairs]
            const ulonglong2 wB = *(const ulonglong2*)(wrow + D);   // W[2i2+1][j pairs]
            #pragma unroll
            for (int t = 0; t < ITEM_TILE; t++) {
                // {x_{2i2} dup, x_{2i2+1} dup} -- one broadcast LDS.128
                const ulonglong2 xp = *(const ulonglong2*)(xd + t * (2 * D) + i2 * 4);
                acc[t][0] = fma2(xp.x, wA.x, acc[t][0]);
                acc[t][1] = fma2(xp.x, wA.y, acc[t][1]);
                acc[t][0] = fma2(xp.y, wB.x, acc[t][0]);
                acc[t][1] = fma2(xp.y, wB.y, acc[t][1]);
            }
        }

        if (iter == 0) {
            __syncwarp();   // all lanes done reading xd before overwrite
            #pragma unroll
            for (int t = 0; t < ITEM_TILE; t++) {
                float a0, a1, a2, a3;
                unpack2(acc[t][0], a0, a1);
                unpack2(acc[t][1], a2, a3);
                const float x0 = mg[t].x + fmaxf(a0, 0.f);
                const float x1 = mg[t].y + fmaxf(a1, 0.f);
                const float x2 = mg[t].z + fmaxf(a2, 0.f);
                const float x3 = mg[t].w + fmaxf(a3, 0.f);
                float4* dst = (float4*)(xd + t * (2 * D) + lane * 8);
                dst[0] = make_float4(x0, x0, x1, x1);
                dst[1] = make_float4(x2, x2, x3, x3);
            }
            __syncwarp();
        }
    }

    // ---- final: sigmoid(dot(u_emb, relu(rep))); reload u_emb (cache-resident) ----
    #pragma unroll
    for (int t = 0; t < ITEM_TILE; t++) {
        const int item = base + t;
        const int cit  = item < B ? item : (B - 1);
        const int iu = u[cit];
        const float4 uex = usr4[(size_t)iu * 32 + lane];

        float a0, a1, a2, a3;
        unpack2(acc[t][0], a0, a1);
        unpack2(acc[t][1], a2, a3);
        float p = uex.x * fmaxf(a0, 0.f)
                + uex.y * fmaxf(a1, 0.f)
                + uex.z * fmaxf(a2, 0.f)
                + uex.w * fmaxf(a3, 0.f);
        #pragma unroll
        for (int o = 16; o > 0; o >>= 1)
            p += __shfl_xor_sync(0xffffffffu, p, o);
        if (lane == 0 && item < B)
            out[item] = 1.f / (1.f + __expf(-p));
    }
}

extern "C" void kernel_launch(void* const* d_in, const int* in_sizes, int n_in,
                              void* d_out, int out_size)
{
    const int*   u       = (const int*)d_in[0];
    const int*   v       = (const int*)d_in[1];
    const int*   adj_ent = (const int*)d_in[2];
    const int*   adj_rel = (const int*)d_in[3];
    const float* usr     = (const float*)d_in[4];
    const float* ent     = (const float*)d_in[5];
    const float* rel     = (const float*)d_in[6];
    const float* W       = (const float*)d_in[7];
    const float* bias    = (const float*)d_in[8];
    float* out = (float*)d_out;

    const int B = in_sizes[0];

    static bool attr_set = false;
    if (!attr_set) {
        cudaFuncSetAttribute(kgcn_kernel,
                             cudaFuncAttributeMaxDynamicSharedMemorySize,
                             SMEM_BYTES);
        attr_set = true;
    }

    dim3 grid((B + ITEMS_PB - 1) / ITEMS_PB);   // 256 blocks, all co-resident
    kgcn_kernel<<<grid, BLOCK_THREADS, SMEM_BYTES>>>(
        u, v, adj_ent, adj_rel, usr, ent, rel, W, bias, out, B);
}

// round 6
// speedup vs baseline: 1.2643x; 1.1145x over previous
#include <cuda_runtime.h>
#include <cuda_bf16.h>
#include <cstdint>

#define D            128
#define S            16
#define WARPS_PB     8
#define ITEM_TILE    4
#define ITEMS_PB     (WARPS_PB * ITEM_TILE)   // 32
#define BLOCK_THREADS (WARPS_PB * 32)         // 256

// smem: W only (16384 floats = 64 KB) -> 2 blocks/SM easily
#define SMEM_BYTES   (D * D * 4)

__global__ __launch_bounds__(BLOCK_THREADS, 2)    // 2 blocks/SM -> 16 warps/SM
void kgcn_kernel(const int* __restrict__ u,
                 const int* __restrict__ v,
                 const int* __restrict__ adj_ent,
                 const int* __restrict__ adj_rel,
                 const float* __restrict__ usr,
                 const float* __restrict__ ent,
                 const float* __restrict__ rel,
                 const float* __restrict__ W,
                 const float* __restrict__ bias,
                 float* __restrict__ out,
                 int B)
{
    extern __shared__ float smem[];
    float* Wsh = smem;                                   // 16384 floats

    const int tid  = threadIdx.x;
    const int lane = tid & 31;
    const int wid  = tid >> 5;

    // ---- stage W into shared (row-major W[i*128 + j]) ----
    {
        const float4* Wg4 = (const float4*)W;
        float4* Ws4 = (float4*)Wsh;
        #pragma unroll
        for (int k = 0; k < (D * D / 4) / BLOCK_THREADS; k++) {
            int i = tid + k * BLOCK_THREADS;
            Ws4[i] = Wg4[i];
        }
    }
    __syncthreads();

    const int base = (blockIdx.x * WARPS_PB + wid) * ITEM_TILE;

    const float4* usr4 = (const float4*)usr;
    const float4* ent4 = (const float4*)ent;
    const float4* rel4 = (const float4*)rel;
    const int4*   adjE4 = (const int4*)adj_ent;          // 4 int4 per row (S=16)
    const int4*   adjR4 = (const int4*)adj_rel;

    // Lane owns dims j = lane*4 + m. All state in registers.
    float4 ue[ITEM_TILE];    // user embedding
    float4 mg[ITEM_TILE];    // normalized neighbor message
    float4 xr[ITEM_TILE];    // current GEMV input x

    #pragma unroll
    for (int t = 0; t < ITEM_TILE; t++) {
        const int item = base + t;
        const int cit  = item < B ? item : (B - 1);   // clamp (deterministic)
        const int iu = u[cit];
        const int iv = v[cit];

        const float4 uex = usr4[(size_t)iu * 32 + lane];
        ue[t] = uex;
        const float4 rp = ent4[(size_t)iv * 32 + lane];

        // adjacency rows via vector broadcasts
        int eix[S], rix[S];
        #pragma unroll
        for (int q = 0; q < 4; q++) {
            const int4 e = __ldg(&adjE4[iv * 4 + q]);
            const int4 r = __ldg(&adjR4[iv * 4 + q]);
            eix[q*4+0] = e.x; eix[q*4+1] = e.y; eix[q*4+2] = e.z; eix[q*4+3] = e.w;
            rix[q*4+0] = r.x; rix[q*4+1] = r.y; rix[q*4+2] = r.z; rix[q*4+3] = r.w;
        }

        // Fused single-pass: score -> exp -> weighted accumulate.
        // Scores are tiny (|p| << 1): exp without max-subtraction is safe
        // (validated rel_err 4.1e-8).
        float sum = 0.f;
        float4 msg = make_float4(0.f, 0.f, 0.f, 0.f);
        #pragma unroll
        for (int s = 0; s < S; s++) {
            const float4 r4 = rel4[(size_t)rix[s] * 32 + lane];
            const float4 e4 = ent4[(size_t)eix[s] * 32 + lane];  // in flight with r4
            float p = uex.x * r4.x + uex.y * r4.y + uex.z * r4.z + uex.w * r4.w;
            #pragma unroll
            for (int o = 16; o > 0; o >>= 1)
                p += __shfl_xor_sync(0xffffffffu, p, o);
            const float es = __expf(p);
            sum += es;
            msg.x = fmaf(es, e4.x, msg.x);
            msg.y = fmaf(es, e4.y, msg.y);
            msg.z = fmaf(es, e4.z, msg.z);
            msg.w = fmaf(es, e4.w, msg.w);
        }
        const float inv = __frcp_rn(sum);
        msg.x *= inv; msg.y *= inv; msg.z *= inv; msg.w *= inv;
        mg[t] = msg;

        // x0 = msg + rep0 (registers only)
        xr[t] = make_float4(msg.x + rp.x, msg.y + rp.y, msg.z + rp.z, msg.w + rp.w);
    }

    const float4 b4 = ((const float4*)bias)[lane];
    float acc[ITEM_TILE][4];
    const float4* Ws4 = (const float4*)Wsh;

    // ---- 2 iterations: rep = relu(x @ W + b); x broadcast via warp shuffles ----
    #pragma unroll
    for (int iter = 0; iter < 2; iter++) {
        #pragma unroll
        for (int t = 0; t < ITEM_TILE; t++) {
            acc[t][0] = b4.x; acc[t][1] = b4.y; acc[t][2] = b4.z; acc[t][3] = b4.w;
        }

        #pragma unroll 2
        for (int i4 = 0; i4 < 32; i4++) {
            // 4 consecutive W rows i = 4*i4 + c
            float4 w0 = Ws4[(4 * i4 + 0) * 32 + lane];
            float4 w1 = Ws4[(4 * i4 + 1) * 32 + lane];
            float4 w2 = Ws4[(4 * i4 + 2) * 32 + lane];
            float4 w3 = Ws4[(4 * i4 + 3) * 32 + lane];
            #pragma unroll
            for (int t = 0; t < ITEM_TILE; t++) {
                // x[t][4*i4+c] lives in lane i4, component c
                const float x0 = __shfl_sync(0xffffffffu, xr[t].x, i4);
                const float x1 = __shfl_sync(0xffffffffu, xr[t].y, i4);
                const float x2 = __shfl_sync(0xffffffffu, xr[t].z, i4);
                const float x3 = __shfl_sync(0xffffffffu, xr[t].w, i4);
                acc[t][0] = fmaf(x0, w0.x, acc[t][0]);
                acc[t][1] = fmaf(x0, w0.y, acc[t][1]);
                acc[t][2] = fmaf(x0, w0.z, acc[t][2]);
                acc[t][3] = fmaf(x0, w0.w, acc[t][3]);
                acc[t][0] = fmaf(x1, w1.x, acc[t][0]);
                acc[t][1] = fmaf(x1, w1.y, acc[t][1]);
                acc[t][2] = fmaf(x1, w1.z, acc[t][2]);
                acc[t][3] = fmaf(x1, w1.w, acc[t][3]);
                acc[t][0] = fmaf(x2, w2.x, acc[t][0]);
                acc[t][1] = fmaf(x2, w2.y, acc[t][1]);
                acc[t][2] = fmaf(x2, w2.z, acc[t][2]);
                acc[t][3] = fmaf(x2, w2.w, acc[t][3]);
                acc[t][0] = fmaf(x3, w3.x, acc[t][0]);
                acc[t][1] = fmaf(x3, w3.y, acc[t][1]);
                acc[t][2] = fmaf(x3, w3.z, acc[t][2]);
                acc[t][3] = fmaf(x3, w3.w, acc[t][3]);
            }
        }

        if (iter == 0) {
            #pragma unroll
            for (int t = 0; t < ITEM_TILE; t++) {
                xr[t].x = mg[t].x + fmaxf(acc[t][0], 0.f);
                xr[t].y = mg[t].y + fmaxf(acc[t][1], 0.f);
                xr[t].z = mg[t].z + fmaxf(acc[t][2], 0.f);
                xr[t].w = mg[t].w + fmaxf(acc[t][3], 0.f);
            }
        }
    }

    // ---- final: sigmoid(dot(u_emb, relu(rep))) ----
    #pragma unroll
    for (int t = 0; t < ITEM_TILE; t++) {
        float p = ue[t].x * fmaxf(acc[t][0], 0.f)
                + ue[t].y * fmaxf(acc[t][1], 0.f)
                + ue[t].z * fmaxf(acc[t][2], 0.f)
                + ue[t].w * fmaxf(acc[t][3], 0.f);
        #pragma unroll
        for (int o = 16; o > 0; o >>= 1)
            p += __shfl_xor_sync(0xffffffffu, p, o);
        const int item = base + t;
        if (lane == 0 && item < B)
            out[item] = 1.f / (1.f + __expf(-p));
    }
}

extern "C" void kernel_launch(void* const* d_in, const int* in_sizes, int n_in,
                              void* d_out, int out_size)
{
    const int*   u       = (const int*)d_in[0];
    const int*   v       = (const int*)d_in[1];
    const int*   adj_ent = (const int*)d_in[2];
    const int*   adj_rel = (const int*)d_in[3];
    const float* usr     = (const float*)d_in[4];
    const float* ent     = (const float*)d_in[5];
    const float* rel     = (const float*)d_in[6];
    const float* W       = (const float*)d_in[7];
    const float* bias    = (const float*)d_in[8];
    float* out = (float*)d_out;

    const int B = in_sizes[0];

    static bool attr_set = false;
    if (!attr_set) {
        cudaFuncSetAttribute(kgcn_kernel,
                             cudaFuncAttributeMaxDynamicSharedMemorySize,
                             SMEM_BYTES);
        attr_set = true;
    }

    dim3 grid((B + ITEMS_PB - 1) / ITEMS_PB);   // 256 blocks (R1's proven shape)
    kgcn_kernel<<<grid, BLOCK_THREADS, SMEM_BYTES>>>(
        u, v, adj_ent, adj_rel, usr, ent, rel, W, bias, out, B);
}

// round 7
// speedup vs baseline: 1.8403x; 1.4556x over previous
#include <cuda_runtime.h>
#include <cuda_bf16.h>
#include <cstdint>

#define D            128
#define S            16
#define WARPS_PB     8
#define ITEM_TILE    4
#define ITEMS_PB     (WARPS_PB * ITEM_TILE)   // 32
#define BLOCK_THREADS (WARPS_PB * 32)         // 256

#define WSTRIDE      136    // W rows padded: conflict-free B-fragment LDS
#define XSTRIDE      132    // X rows padded: conflict-free A-fragment LDS

#define W_FLOATS     (D * WSTRIDE)            // 17408
#define X_FLOATS     (ITEMS_PB * XSTRIDE)     // 4224
#define SMEM_FLOATS  (W_FLOATS + 2 * X_FLOATS)
#define SMEM_BYTES   (SMEM_FLOATS * 4)        // 103424 -> 2 blocks/SM (206848 B)

__device__ __forceinline__ uint32_t f2tf32(float f) {
    uint32_t r;
    asm("cvt.rna.tf32.f32 %0, %1;" : "=r"(r) : "f"(f));
    return r;
}

__device__ __forceinline__ void mma_tf32(float acc[4], const uint32_t a[4],
                                         const uint32_t b[2]) {
    asm("mma.sync.aligned.m16n8k8.row.col.f32.tf32.tf32.f32 "
        "{%0,%1,%2,%3}, {%4,%5,%6,%7}, {%8,%9}, {%0,%1,%2,%3};"
        : "+f"(acc[0]), "+f"(acc[1]), "+f"(acc[2]), "+f"(acc[3])
        : "r"(a[0]), "r"(a[1]), "r"(a[2]), "r"(a[3]),
          "r"(b[0]), "r"(b[1]));
}

__global__ __launch_bounds__(BLOCK_THREADS, 2)     // 16 warps/SM (proven best)
void kgcn_kernel(const int* __restrict__ u,
                 const int* __restrict__ v,
                 const int* __restrict__ adj_ent,
                 const int* __restrict__ adj_rel,
                 const float* __restrict__ usr,
                 const float* __restrict__ ent,
                 const float* __restrict__ rel,
                 const float* __restrict__ W,
                 const float* __restrict__ bias,
                 float* __restrict__ out,
                 int B)
{
    extern __shared__ char smraw[];
    uint32_t* Wsh = (uint32_t*)smraw;                       // tf32 W [128][136]
    uint32_t* Xsh = (uint32_t*)(smraw + W_FLOATS * 4);      // tf32 X [32][132]
    float*    Msh = (float*)   (smraw + (W_FLOATS + X_FLOATS) * 4); // msg [32][132]
    float*    Hsh = Msh;   // reused for relu(h2) in the epilogue

    const int tid  = threadIdx.x;
    const int lane = tid & 31;
    const int wid  = tid >> 5;
    const int g    = lane >> 2;    // fragment group id (0..7)
    const int tq   = lane & 3;     // thread-in-group (0..3)

    // ---- stage W -> shared, tf32-rounded, padded stride ----
    {
        const float4* Wg4 = (const float4*)W;
        #pragma unroll
        for (int k = 0; k < (D * D / 4) / BLOCK_THREADS; k++) {
            const int i = tid + k * BLOCK_THREADS;
            const float4 w = Wg4[i];
            const int row = (i * 4) >> 7;
            const int col = (i * 4) & 127;
            uint32_t* p = Wsh + row * WSTRIDE + col;
            p[0] = f2tf32(w.x); p[1] = f2tf32(w.y);
            p[2] = f2tf32(w.z); p[3] = f2tf32(w.w);
        }
    }

    const int base = (blockIdx.x * WARPS_PB + wid) * ITEM_TILE;

    const float4* usr4 = (const float4*)usr;
    const float4* ent4 = (const float4*)ent;
    const float4* rel4 = (const float4*)rel;
    const int4*   adjE4 = (const int4*)adj_ent;
    const int4*   adjR4 = (const int4*)adj_rel;

    float4 ue[ITEM_TILE];   // user embedding (kept in regs through epilogue)

    // ================= gather + attention phase (per-warp, 4 items) =========
    #pragma unroll
    for (int t = 0; t < ITEM_TILE; t++) {
        const int item = base + t;
        const int cit  = item < B ? item : (B - 1);
        const int iu = u[cit];
        const int iv = v[cit];

        const float4 uex = usr4[(size_t)iu * 32 + lane];
        ue[t] = uex;
        const float4 rp = ent4[(size_t)iv * 32 + lane];

        int eix[S], rix[S];
        #pragma unroll
        for (int q = 0; q < 4; q++) {
            const int4 e = __ldg(&adjE4[iv * 4 + q]);
            const int4 r = __ldg(&adjR4[iv * 4 + q]);
            eix[q*4+0] = e.x; eix[q*4+1] = e.y; eix[q*4+2] = e.z; eix[q*4+3] = e.w;
            rix[q*4+0] = r.x; rix[q*4+1] = r.y; rix[q*4+2] = r.z; rix[q*4+3] = r.w;
        }

        // fused single-pass: score -> exp -> weighted accumulate
        // (scores tiny; no-max-sub exp validated at rel_err 4.1e-8)
        float sum = 0.f;
        float4 msg = make_float4(0.f, 0.f, 0.f, 0.f);
        #pragma unroll
        for (int s = 0; s < S; s++) {
            const float4 r4 = rel4[(size_t)rix[s] * 32 + lane];
            const float4 e4 = ent4[(size_t)eix[s] * 32 + lane];
            float p = uex.x * r4.x + uex.y * r4.y + uex.z * r4.z + uex.w * r4.w;
            #pragma unroll
            for (int o = 16; o > 0; o >>= 1)
                p += __shfl_xor_sync(0xffffffffu, p, o);
            const float es = __expf(p);
            sum += es;
            msg.x = fmaf(es, e4.x, msg.x);
            msg.y = fmaf(es, e4.y, msg.y);
            msg.z = fmaf(es, e4.z, msg.z);
            msg.w = fmaf(es, e4.w, msg.w);
        }
        const float inv = __frcp_rn(sum);
        msg.x *= inv; msg.y *= inv; msg.z *= inv; msg.w *= inv;

        const int row = wid * ITEM_TILE + t;        // block-local item row
        // msg (fp32) for the residual adds
        ((float4*)(Msh + row * XSTRIDE))[lane] = msg;
        // x0 = msg + rep0, tf32-rounded for the mma
        uint32_t* xp = Xsh + row * XSTRIDE + lane * 4;
        xp[0] = f2tf32(msg.x + rp.x);
        xp[1] = f2tf32(msg.y + rp.y);
        xp[2] = f2tf32(msg.z + rp.z);
        xp[3] = f2tf32(msg.w + rp.w);
    }
    __syncthreads();

    // ================= GEMM phase: h = X @ W + b, 2 layers ==================
    // block GEMM M=32, N=128, K=128; warp owns 16 N-cols (nt = 2*wid, 2*wid+1)
    const int ncol0 = wid * 16;
    float bb[2][2];
    #pragma unroll
    for (int nt = 0; nt < 2; nt++) {
        bb[nt][0] = __ldg(&bias[ncol0 + nt * 8 + tq * 2]);
        bb[nt][1] = __ldg(&bias[ncol0 + nt * 8 + tq * 2 + 1]);
    }

    float acc[2][2][4];   // [mt][nt][frag]

    #pragma unroll
    for (int iter = 0; iter < 2; iter++) {
        #pragma unroll
        for (int mt = 0; mt < 2; mt++)
            #pragma unroll
            for (int nt = 0; nt < 2; nt++) {
                acc[mt][nt][0] = bb[nt][0]; acc[mt][nt][1] = bb[nt][1];
                acc[mt][nt][2] = bb[nt][0]; acc[mt][nt][3] = bb[nt][1];
            }

        #pragma unroll 4
        for (int kt = 0; kt < 16; kt++) {
            uint32_t a[2][4];
            #pragma unroll
            for (int mt = 0; mt < 2; mt++) {
                const uint32_t* xb = Xsh + (mt * 16 + g) * XSTRIDE + kt * 8 + tq;
                a[mt][0] = xb[0];
                a[mt][1] = xb[8 * XSTRIDE];
                a[mt][2] = xb[4];
                a[mt][3] = xb[8 * XSTRIDE + 4];
            }
            uint32_t b[2][2];
            #pragma unroll
            for (int nt = 0; nt < 2; nt++) {
                const uint32_t* wb = Wsh + (kt * 8 + tq) * WSTRIDE + ncol0 + nt * 8 + g;
                b[nt][0] = wb[0];
                b[nt][1] = wb[4 * WSTRIDE];
            }
            #pragma unroll
            for (int mt = 0; mt < 2; mt++)
                #pragma unroll
                for (int nt = 0; nt < 2; nt++)
                    mma_tf32(acc[mt][nt], a[mt], b[nt]);
        }

        __syncthreads();   // all A-fragment reads of Xsh done

        if (iter == 0) {
            // x1 = msg + relu(h1)  (warp owns cols [ncol0, ncol0+16))
            #pragma unroll
            for (int mt = 0; mt < 2; mt++) {
                #pragma unroll
                for (int nt = 0; nt < 2; nt++) {
                    const int c0 = ncol0 + nt * 8 + tq * 2;
                    const int r0 = mt * 16 + g;
                    const int r1 = r0 + 8;
                    Xsh[r0 * XSTRIDE + c0    ] = f2tf32(Msh[r0 * XSTRIDE + c0    ] + fmaxf(acc[mt][nt][0], 0.f));
                    Xsh[r0 * XSTRIDE + c0 + 1] = f2tf32(Msh[r0 * XSTRIDE + c0 + 1] + fmaxf(acc[mt][nt][1], 0.f));
                    Xsh[r1 * XSTRIDE + c0    ] = f2tf32(Msh[r1 * XSTRIDE + c0    ] + fmaxf(acc[mt][nt][2], 0.f));
                    Xsh[r1 * XSTRIDE + c0 + 1] = f2tf32(Msh[r1 * XSTRIDE + c0 + 1] + fmaxf(acc[mt][nt][3], 0.f));
                }
            }
            __syncthreads();
        }
    }

    // rep2 = relu(h2) -> Hsh (fp32; overwrites Msh, warp-private columns)
    #pragma unroll
    for (int mt = 0; mt < 2; mt++) {
        #pragma unroll
        for (int nt = 0; nt < 2; nt++) {
            const int c0 = ncol0 + nt * 8 + tq * 2;
            const int r0 = mt * 16 + g;
            const int r1 = r0 + 8;
            Hsh[r0 * XSTRIDE + c0    ] = fmaxf(acc[mt][nt][0], 0.f);
            Hsh[r0 * XSTRIDE + c0 + 1] = fmaxf(acc[mt][nt][1], 0.f);
            Hsh[r1 * XSTRIDE + c0    ] = fmaxf(acc[mt][nt][2], 0.f);
            Hsh[r1 * XSTRIDE + c0 + 1] = fmaxf(acc[mt][nt][3], 0.f);
        }
    }
    __syncthreads();

    // ================= epilogue: sigmoid(dot(u_emb, rep2)) ==================
    #pragma unroll
    for (int t = 0; t < ITEM_TILE; t++) {
        const int row = wid * ITEM_TILE + t;
        const float4 h = ((const float4*)(Hsh + row * XSTRIDE))[lane];
        float p = ue[t].x * h.x + ue[t].y * h.y + ue[t].z * h.z + ue[t].w * h.w;
        #pragma unroll
        for (int o = 16; o > 0; o >>= 1)
            p += __shfl_xor_sync(0xffffffffu, p, o);
        const int item = base + t;
        if (lane == 0 && item < B)
            out[item] = 1.f / (1.f + __expf(-p));
    }
}

extern "C" void kernel_launch(void* const* d_in, const int* in_sizes, int n_in,
                              void* d_out, int out_size)
{
    const int*   u       = (const int*)d_in[0];
    const int*   v       = (const int*)d_in[1];
    const int*   adj_ent = (const int*)d_in[2];
    const int*   adj_rel = (const int*)d_in[3];
    const float* usr     = (const float*)d_in[4];
    const float* ent     = (const float*)d_in[5];
    const float* rel     = (const float*)d_in[6];
    const float* W       = (const float*)d_in[7];
    const float* bias    = (const float*)d_in[8];
    float* out = (float*)d_out;

    const int B = in_sizes[0];

    static bool attr_set = false;
    if (!attr_set) {
        cudaFuncSetAttribute(kgcn_kernel,
                             cudaFuncAttributeMaxDynamicSharedMemorySize,
                             SMEM_BYTES);
        attr_set = true;
    }

    dim3 grid((B + ITEMS_PB - 1) / ITEMS_PB);   // 256 blocks, 2/SM
    kgcn_kernel<<<grid, BLOCK_THREADS, SMEM_BYTES>>>(
        u, v, adj_ent, adj_rel, usr, ent, rel, W, bias, out, B);
}